// round 5
// baseline (speedup 1.0000x reference)
#include <cuda_runtime.h>
#include <cuda_bf16.h>
#include <cstdint>

#define SEQ   512
#define BAT   64
#define DH    1024
#define KP    3072                 // tri-split K' = 3*1024
#define MROWS (SEQ*BAT)            // 32768
#define BHD   (BAT*DH)             // 65536

#define GRID_REC 128
#define REC_THREADS 256
#define KS_ZR 4                    // zr chunk = 768
#define KS_N  8                    // n  chunk = 384
#define CH_ZR 768
#define CH_N  384
#define WPSZ  ((size_t)DH*KP)
#define LDT   72                   // W stage row stride (bf16)
#define LDA   776                  // resident A row stride (bf16), 776*2=1552=16*97
#define NITA  (CH_ZR/64)           // 12
#define NITC  (CH_N/64)            // 6
#define REC_SMEM (64*LDA*2 + 3*64*LDT*2)   // 99328 + 27648 = 126976

// ---------------- device globals (no allocations allowed) -------------------
__device__ __nv_bfloat16 g_xp [(size_t)MROWS*KP];   // x tri-split (hi,lo,hi)
__device__ __nv_bfloat16 g_hsp[(size_t)MROWS*KP];   // hs tri-split
__device__ __nv_bfloat16 g_wp [7*WPSZ];             // weights tri-split (hi,hi,lo)
__device__ float g_xz[(size_t)SEQ*BHD];
__device__ float g_xr[(size_t)SEQ*BHD];
__device__ float g_xn[(size_t)SEQ*BHD];
__device__ float g_h [BHD];
__device__ __nv_bfloat16 g_hp [BAT*KP];             // h tri-split
__device__ float g_pzr[2*KS_ZR*(size_t)BHD];        // z,r split-K partials
__device__ float g_pn [KS_N*(size_t)BHD];           // n split-K partials
__device__ unsigned g_barcnt;
__device__ volatile unsigned g_barsense;

// ---------------- helpers ----------------------------------------------------
__device__ __forceinline__ void trisplit(float v, __nv_bfloat16& hi, __nv_bfloat16& lo) {
    hi = __float2bfloat16(v);
    lo = __float2bfloat16(v - __bfloat162float(hi));
}

__device__ __forceinline__ uint32_t smem_u32(const void* p) {
    return (uint32_t)__cvta_generic_to_shared(p);
}

__device__ __forceinline__ void ldsm_x4(uint32_t* r, uint32_t addr) {
    asm volatile("ldmatrix.sync.aligned.m8n8.x4.shared.b16 {%0,%1,%2,%3}, [%4];"
                 : "=r"(r[0]), "=r"(r[1]), "=r"(r[2]), "=r"(r[3]) : "r"(addr));
}

__device__ __forceinline__ void mma_bf16(float* d, const uint32_t* a,
                                         uint32_t b0, uint32_t b1) {
    asm volatile("mma.sync.aligned.m16n8k16.row.col.f32.bf16.bf16.f32 "
                 "{%0,%1,%2,%3},{%4,%5,%6,%7},{%8,%9},{%0,%1,%2,%3};"
                 : "+f"(d[0]), "+f"(d[1]), "+f"(d[2]), "+f"(d[3])
                 : "r"(a[0]), "r"(a[1]), "r"(a[2]), "r"(a[3]), "r"(b0), "r"(b1));
}

__device__ __forceinline__ void cp_async16(uint32_t saddr, const void* gptr) {
    asm volatile("cp.async.cg.shared.global [%0], [%1], 16;" :: "r"(saddr), "l"(gptr));
}
__device__ __forceinline__ void cp_commit() {
    asm volatile("cp.async.commit_group;");
}
template <int N>
__device__ __forceinline__ void cp_wait() {
    asm volatile("cp.async.wait_group %0;" :: "n"(N));
}

// ---------------- conversion kernels ----------------------------------------
__global__ void conv_a_kernel(const float* __restrict__ x) {
    size_t i = (size_t)blockIdx.x * 256 + threadIdx.x;
    float v = x[i];
    size_t m = i >> 10, k = i & 1023;
    __nv_bfloat16 hi, lo; trisplit(v, hi, lo);
    __nv_bfloat16* dst = g_xp + m * KP;
    dst[k] = hi; dst[1024 + k] = lo; dst[2048 + k] = hi;
}

__global__ void conv_w_kernel(const float* w0, const float* w1, const float* w2,
                              const float* w3, const float* w4, const float* w5,
                              const float* w6) {
    int z = blockIdx.z;
    const float* src = (z==0)?w0:(z==1)?w1:(z==2)?w2:(z==3)?w3:(z==4)?w4:(z==5)?w5:w6;
    size_t i = (size_t)blockIdx.x * 256 + threadIdx.x;
    float v = src[i];
    size_t row = i >> 10, k = i & 1023;
    __nv_bfloat16 hi, lo; trisplit(v, hi, lo);
    __nv_bfloat16* dst = g_wp + (size_t)z * WPSZ + row * KP;
    dst[k] = hi; dst[1024 + k] = hi; dst[2048 + k] = lo;
}

// ---------------- init -------------------------------------------------------
__global__ void init_h_kernel(const float* __restrict__ h0) {
    int i = blockIdx.x * 256 + threadIdx.x;
    float v = h0[i];
    g_h[i] = v;
    int b = i >> 10, k = i & 1023;
    __nv_bfloat16 hi, lo; trisplit(v, hi, lo);
    __nv_bfloat16* dst = g_hp + (size_t)b * KP;
    dst[k] = hi; dst[1024 + k] = lo; dst[2048 + k] = hi;
    if (i == 0) { g_barcnt = 0; g_barsense = 0; }
}

// ---------------- grid barrier ----------------------------------------------
__device__ __forceinline__ void gbar(unsigned& phase) {
    phase++;
    __threadfence();
    __syncthreads();
    if (threadIdx.x == 0) {
        unsigned a = atomicAdd(&g_barcnt, 1);
        if (a == GRID_REC - 1) {
            g_barcnt = 0;
            __threadfence();
            g_barsense = phase;
        } else {
            while (g_barsense != phase) { __nanosleep(32); }
        }
    }
    __syncthreads();
    __threadfence();
}

// ---------------- big bf16 GEMM (unchanged from round 3) --------------------
__global__ __launch_bounds__(256)
void gemm_bf16p(int a_sel, int w_base, int c_mode,
                const float* __restrict__ bias0, const float* __restrict__ bias1,
                const float* __restrict__ bias2, float* __restrict__ Cext) {
    const int z = blockIdx.z;
    const __nv_bfloat16* A = a_sel ? g_hsp : g_xp;
    const __nv_bfloat16* W = g_wp + (size_t)(w_base + z) * WPSZ;
    const float* bias = (z == 0) ? bias0 : (z == 1) ? bias1 : bias2;
    float* C = (c_mode == 1) ? Cext : (z == 0 ? g_xz : z == 1 ? g_xr : g_xn);

    __shared__ __nv_bfloat16 As[128 * LDT];
    __shared__ __nv_bfloat16 Bs[64 * LDT];

    const int m0 = blockIdx.y * 128, n0 = blockIdx.x * 64;
    const int t = threadIdx.x, lane = t & 31, w8 = t >> 5;
    const int wm = w8 >> 1, wn = w8 & 1;
    const int lr = t >> 3, lq = t & 7;

    float acc[2][4][4] = {};

    for (int k0 = 0; k0 < KP; k0 += 64) {
        #pragma unroll
        for (int p = 0; p < 4; ++p) {
            int r = lr + p * 32;
            ((uint4*)(As + r * LDT))[lq] =
                *((const uint4*)(A + (size_t)(m0 + r) * KP + k0) + lq);
        }
        #pragma unroll
        for (int p = 0; p < 2; ++p) {
            int r = lr + p * 32;
            ((uint4*)(Bs + r * LDT))[lq] =
                *((const uint4*)(W + (size_t)(n0 + r) * KP + k0) + lq);
        }
        __syncthreads();
        #pragma unroll
        for (int kk = 0; kk < 4; ++kk) {
            const int ks = kk * 16;
            uint32_t aF[2][4], bF[2][4];
            #pragma unroll
            for (int mi = 0; mi < 2; ++mi) {
                int arow = wm * 32 + mi * 16 + (lane & 15);
                int acol = ks + ((lane >> 4) << 3);
                ldsm_x4(aF[mi], smem_u32(As + arow * LDT + acol));
            }
            #pragma unroll
            for (int nq = 0; nq < 2; ++nq) {
                int brow = wn * 32 + nq * 16 + (lane & 7) + (((lane >> 4) & 1) << 3);
                int bcol = ks + (((lane >> 3) & 1) << 3);
                ldsm_x4(bF[nq], smem_u32(Bs + brow * LDT + bcol));
            }
            #pragma unroll
            for (int mi = 0; mi < 2; ++mi)
                #pragma unroll
                for (int nq = 0; nq < 2; ++nq) {
                    mma_bf16(acc[mi][2 * nq],     aF[mi], bF[nq][0], bF[nq][1]);
                    mma_bf16(acc[mi][2 * nq + 1], aF[mi], bF[nq][2], bF[nq][3]);
                }
        }
        __syncthreads();
    }

    #pragma unroll
    for (int mi = 0; mi < 2; ++mi)
        #pragma unroll
        for (int ni = 0; ni < 4; ++ni) {
            int row = m0 + wm * 32 + mi * 16 + (lane >> 2);
            int col = n0 + wn * 32 + ni * 8 + (lane & 3) * 2;
            float b0 = bias[col], b1 = bias[col + 1];
            float* a = acc[mi][ni];
            *(float2*)&C[(size_t)row * DH + col]       = make_float2(a[0] + b0, a[1] + b1);
            *(float2*)&C[(size_t)(row + 8) * DH + col] = make_float2(a[2] + b0, a[3] + b1);
        }
}

// ---------------- recurrence GEMM core: A resident in smem, W streamed ------
// 8 warps (2m x 4n), warp tile 32x16 -> 64x64 output. acc[2][2][4].
__device__ __forceinline__ void gemm_w_stream(
    const __nv_bfloat16* __restrict__ Wg,   // weight rows n0..n0+63, pitch KP
    int k0, int nit,
    const __nv_bfloat16* sA,                // [64][LDA]
    __nv_bfloat16 (*sW)[64 * LDT],
    float acc[2][2][4]) {
    const int t = threadIdx.x, lane = t & 31, w8 = t >> 5;
    const int wm = w8 >> 2, wn = w8 & 3;

    auto loadW = [&](int st, int kt) {
        #pragma unroll
        for (int h = 0; h < 2; ++h) {
            int c = t + h * 256;               // 512 chunks of 16B = 64x64 bf16
            int row = c >> 3, off = (c & 7) * 8;
            cp_async16(smem_u32(&sW[st][row * LDT + off]),
                       Wg + (size_t)row * KP + k0 + kt * 64 + off);
        }
        cp_commit();
    };

    loadW(0, 0);
    loadW(1, 1);

    for (int kt = 0; kt < nit; ++kt) {
        cp_wait<1>();
        __syncthreads();
        const int st = kt % 3;
        #pragma unroll
        for (int kk = 0; kk < 4; ++kk) {
            const int ks16 = kk * 16;
            uint32_t bF[4];
            int brow = wn * 16 + (lane & 7) + (((lane >> 4) & 1) << 3);
            int bcol = ks16 + (((lane >> 3) & 1) << 3);
            ldsm_x4(bF, smem_u32(&sW[st][brow * LDT + bcol]));
            #pragma unroll
            for (int mi = 0; mi < 2; ++mi) {
                uint32_t aF[4];
                int arow = wm * 32 + mi * 16 + (lane & 15);
                int acol = kt * 64 + ks16 + ((lane >> 4) << 3);
                ldsm_x4(aF, smem_u32(&sA[arow * LDA + acol]));
                mma_bf16(acc[mi][0], aF, bF[0], bF[1]);
                mma_bf16(acc[mi][1], aF, bF[2], bF[3]);
            }
        }
        if (kt + 2 < nit) loadW((kt + 2) % 3, kt + 2);
        else cp_commit();
        __syncthreads();
    }
}

__device__ __forceinline__ void store_partial(
    float* __restrict__ part, int n0, const float acc[2][2][4]) {
    const int lane = threadIdx.x & 31, w8 = threadIdx.x >> 5;
    const int wm = w8 >> 2, wn = w8 & 3;
    #pragma unroll
    for (int mi = 0; mi < 2; ++mi)
        #pragma unroll
        for (int ni = 0; ni < 2; ++ni) {
            int row = wm * 32 + mi * 16 + (lane >> 2);
            int col = n0 + wn * 16 + ni * 8 + (lane & 3) * 2;
            const float* a = acc[mi][ni];
            *(float2*)&part[(size_t)row * DH + col]       = make_float2(a[0], a[1]);
            *(float2*)&part[(size_t)(row + 8) * DH + col] = make_float2(a[2], a[3]);
        }
}

// ---------------- persistent recurrence (3 phases / 3 barriers per step) ----
__global__ __launch_bounds__(REC_THREADS)
void recurrence_kernel() {
    extern __shared__ char dynbuf[];
    __nv_bfloat16* sA = (__nv_bfloat16*)dynbuf;
    __nv_bfloat16 (*sW)[64 * LDT] =
        (__nv_bfloat16 (*)[64 * LDT])(dynbuf + 64 * LDA * 2);

    const int bid = blockIdx.x;
    const int tid = threadIdx.x;
    unsigned phase = 0;

    // phase A: gate(2) x ntile(16 of 64 cols) x ks(4 of 768)
    const int gateA  = bid >> 6;
    const int ntileA = (bid & 63) >> 2;
    const int ksA    = bid & 3;
    const int n0A    = ntileA * 64;
    const int k0A    = ksA * CH_ZR;
    const __nv_bfloat16* WA = g_wp + (size_t)(3 + gateA) * WPSZ + (size_t)n0A * KP;
    float* partA = g_pzr + (size_t)(gateA * KS_ZR + ksA) * BHD;

    // phase C: ntile(16 of 64 cols) x ks(8 of 384)
    const int ntileC = bid >> 3;
    const int ksC    = bid & 7;
    const int n0C    = ntileC * 64;
    const int k0C    = ksC * CH_N;
    const __nv_bfloat16* WC = g_wp + (size_t)5 * WPSZ + (size_t)n0C * KP;
    float* partC = g_pn + (size_t)ksC * BHD;

    for (int s = 0; s < SEQ; ++s) {
        // ============ phase A: z,r partial GEMMs ============
        {
            // preload A = g_hp[:, k0A:k0A+768] into smem (one cp.async group)
            for (int c = tid; c < 64 * (CH_ZR / 8); c += REC_THREADS) {
                int row = c / (CH_ZR / 8);           // 96 chunks per row
                int off = (c - row * (CH_ZR / 8)) * 8;
                cp_async16(smem_u32(&sA[row * LDA + off]),
                           g_hp + (size_t)row * KP + k0A + off);
            }
            cp_commit();
            float acc[2][2][4] = {};
            gemm_w_stream(WA, k0A, NITA, sA, sW, acc);
            store_partial(partA, n0A, acc);
        }
        gbar(phase);

        // ============ phase C: build rh tile in smem, then n partial GEMM ====
        {
            const float* xr = g_xr + (size_t)s * BHD;
            for (int i = tid; i < 64 * CH_N; i += REC_THREADS) {
                int row = i / CH_N;
                int c   = i - row * CH_N;
                int p   = k0C + c;
                int l   = p & 1023;
                int typ = p >> 10;                    // 0 hi, 1 lo, 2 hi
                int idx = row * DH + l;
                float tr = g_pzr[(size_t)(KS_ZR + 0) * BHD + idx]
                         + g_pzr[(size_t)(KS_ZR + 1) * BHD + idx]
                         + g_pzr[(size_t)(KS_ZR + 2) * BHD + idx]
                         + g_pzr[(size_t)(KS_ZR + 3) * BHD + idx];
                float r = 1.f / (1.f + __expf(-(xr[idx] + tr)));
                float rh = r * g_h[idx];
                __nv_bfloat16 hi, lo; trisplit(rh, hi, lo);
                sA[row * LDA + c] = (typ == 1) ? lo : hi;
            }
            __syncthreads();
            float acc[2][2][4] = {};
            gemm_w_stream(WC, k0C, NITC, sA, sW, acc);
            store_partial(partC, n0C, acc);
        }
        gbar(phase);

        // ============ phase D: reduce z,n + h update ============
        {
            const float* xz = g_xz + (size_t)s * BHD;
            const float* xn = g_xn + (size_t)s * BHD;
            #pragma unroll
            for (int q = 0; q < 2; ++q) {
                int i = bid * 512 + q * 256 + tid;
                float tz = g_pzr[i] + g_pzr[(size_t)1 * BHD + i]
                         + g_pzr[(size_t)2 * BHD + i] + g_pzr[(size_t)3 * BHD + i];
                float tn = 0.f;
                #pragma unroll
                for (int ks = 0; ks < KS_N; ++ks)
                    tn += g_pn[(size_t)ks * BHD + i];
                float zv = 1.f / (1.f + __expf(-(xz[i] + tz)));
                float nv = tanhf(xn[i] + tn);
                float h  = g_h[i];
                float hn = fmaf(zv, nv - h, h);
                g_h[i] = hn;
                int b = i >> 10, k = i & 1023;
                __nv_bfloat16 hi, lo; trisplit(hn, hi, lo);
                __nv_bfloat16* dh = g_hp + (size_t)b * KP;
                dh[k] = hi; dh[1024 + k] = lo; dh[2048 + k] = hi;
                __nv_bfloat16* ds = g_hsp + ((size_t)s * BAT + b) * KP;
                ds[k] = hi; ds[1024 + k] = lo; ds[2048 + k] = hi;
            }
        }
        gbar(phase);
    }
}

__global__ void copy_hlast_kernel(float* __restrict__ dst) {
    int i = blockIdx.x * 256 + threadIdx.x;
    dst[i] = g_h[i];
}

// ---------------- launch ----------------------------------------------------
extern "C" void kernel_launch(void* const* d_in, const int* in_sizes, int n_in,
                              void* d_out, int out_size) {
    const float* x   = (const float*)d_in[0];
    const float* h0  = (const float*)d_in[1];
    const float* Wxz = (const float*)d_in[2];
    const float* bxz = (const float*)d_in[3];
    const float* Whz = (const float*)d_in[4];
    const float* Wxr = (const float*)d_in[5];
    const float* bxr = (const float*)d_in[6];
    const float* Whr = (const float*)d_in[7];
    const float* Wxn = (const float*)d_in[8];
    const float* bxn = (const float*)d_in[9];
    const float* Whn = (const float*)d_in[10];
    const float* Why = (const float*)d_in[11];
    const float* bhy = (const float*)d_in[12];
    float* out = (float*)d_out;

    static bool attr_done = false;
    if (!attr_done) {
        cudaFuncSetAttribute(recurrence_kernel,
                             cudaFuncAttributeMaxDynamicSharedMemorySize, REC_SMEM);
        attr_done = true;
    }

    conv_w_kernel<<<dim3(DH * DH / 256, 1, 7), 256>>>(Wxz, Wxr, Wxn, Whz, Whr, Whn, Why);
    conv_a_kernel<<<(size_t)MROWS * DH / 256, 256>>>(x);
    init_h_kernel<<<BHD / 256, 256>>>(h0);

    gemm_bf16p<<<dim3(DH / 64, MROWS / 128, 3), 256>>>(
        0, 0, 0, bxz, bxr, bxn, nullptr);

    recurrence_kernel<<<GRID_REC, REC_THREADS, REC_SMEM>>>();

    gemm_bf16p<<<dim3(DH / 64, MROWS / 128, 1), 256>>>(
        1, 6, 1, bhy, bhy, bhy, out);

    copy_hlast_kernel<<<BHD / 256, 256>>>(out + (size_t)MROWS * DH);
}

// round 6
// speedup vs baseline: 2.6480x; 2.6480x over previous
#include <cuda_runtime.h>
#include <cuda_bf16.h>
#include <cstdint>

#define SEQ   512
#define BAT   64
#define DH    1024
#define KP    3072                 // tri-split K' = 3*1024
#define MROWS (SEQ*BAT)            // 32768
#define BHD   (BAT*DH)             // 65536

#define GRID_REC 128
#define REC_THREADS 256
#define KS_ZR 8                    // zr chunk = 384
#define KS_N  16                   // n  chunk = 192
#define CH_ZR 384
#define CH_N  192
#define WPSZ  ((size_t)DH*KP)
#define LDT   72                   // smem row stride (bf16)
#define REC_SMEM (3*(64+128)*LDT*2)   // 82944

// ---------------- device globals (no allocations allowed) -------------------
__device__ __nv_bfloat16 g_xp [(size_t)MROWS*KP];   // x tri-split (hi,lo,hi)
__device__ __nv_bfloat16 g_hsp[(size_t)MROWS*KP];   // hs tri-split
__device__ __nv_bfloat16 g_wp [7*WPSZ];             // weights tri-split (hi,hi,lo)
__device__ float g_xz[(size_t)SEQ*BHD];
__device__ float g_xr[(size_t)SEQ*BHD];
__device__ float g_xn[(size_t)SEQ*BHD];
__device__ float g_h [BHD];
__device__ __nv_bfloat16 g_hp [BAT*KP];             // h tri-split
__device__ __nv_bfloat16 g_rhp[BAT*KP];             // r*h tri-split
__device__ float g_pzr[2*KS_ZR*(size_t)BHD];        // z,r split-K partials (4MB)
__device__ float g_pn [KS_N*(size_t)BHD];           // n split-K partials (4MB)
__device__ unsigned g_barcnt;
__device__ volatile unsigned g_barsense;

// ---------------- helpers ----------------------------------------------------
__device__ __forceinline__ void trisplit(float v, __nv_bfloat16& hi, __nv_bfloat16& lo) {
    hi = __float2bfloat16(v);
    lo = __float2bfloat16(v - __bfloat162float(hi));
}

__device__ __forceinline__ uint32_t smem_u32(const void* p) {
    return (uint32_t)__cvta_generic_to_shared(p);
}

__device__ __forceinline__ void ldsm_x4(uint32_t* r, uint32_t addr) {
    asm volatile("ldmatrix.sync.aligned.m8n8.x4.shared.b16 {%0,%1,%2,%3}, [%4];"
                 : "=r"(r[0]), "=r"(r[1]), "=r"(r[2]), "=r"(r[3]) : "r"(addr));
}

__device__ __forceinline__ void mma_bf16(float* d, const uint32_t* a,
                                         uint32_t b0, uint32_t b1) {
    asm volatile("mma.sync.aligned.m16n8k16.row.col.f32.bf16.bf16.f32 "
                 "{%0,%1,%2,%3},{%4,%5,%6,%7},{%8,%9},{%0,%1,%2,%3};"
                 : "+f"(d[0]), "+f"(d[1]), "+f"(d[2]), "+f"(d[3])
                 : "r"(a[0]), "r"(a[1]), "r"(a[2]), "r"(a[3]), "r"(b0), "r"(b1));
}

__device__ __forceinline__ void cp_async16(uint32_t saddr, const void* gptr) {
    asm volatile("cp.async.cg.shared.global [%0], [%1], 16;" :: "r"(saddr), "l"(gptr));
}
__device__ __forceinline__ void cp_commit() {
    asm volatile("cp.async.commit_group;");
}
template <int N>
__device__ __forceinline__ void cp_wait() {
    asm volatile("cp.async.wait_group %0;" :: "n"(N));
}

// ---------------- conversion kernels ----------------------------------------
__global__ void conv_a_kernel(const float* __restrict__ x) {
    size_t i = (size_t)blockIdx.x * 256 + threadIdx.x;
    float v = x[i];
    size_t m = i >> 10, k = i & 1023;
    __nv_bfloat16 hi, lo; trisplit(v, hi, lo);
    __nv_bfloat16* dst = g_xp + m * KP;
    dst[k] = hi; dst[1024 + k] = lo; dst[2048 + k] = hi;
}

__global__ void conv_w_kernel(const float* w0, const float* w1, const float* w2,
                              const float* w3, const float* w4, const float* w5,
                              const float* w6) {
    int z = blockIdx.z;
    const float* src = (z==0)?w0:(z==1)?w1:(z==2)?w2:(z==3)?w3:(z==4)?w4:(z==5)?w5:w6;
    size_t i = (size_t)blockIdx.x * 256 + threadIdx.x;
    float v = src[i];
    size_t row = i >> 10, k = i & 1023;
    __nv_bfloat16 hi, lo; trisplit(v, hi, lo);
    __nv_bfloat16* dst = g_wp + (size_t)z * WPSZ + row * KP;
    dst[k] = hi; dst[1024 + k] = hi; dst[2048 + k] = lo;
}

// ---------------- init -------------------------------------------------------
__global__ void init_h_kernel(const float* __restrict__ h0) {
    int i = blockIdx.x * 256 + threadIdx.x;
    float v = h0[i];
    g_h[i] = v;
    int b = i >> 10, k = i & 1023;
    __nv_bfloat16 hi, lo; trisplit(v, hi, lo);
    __nv_bfloat16* dst = g_hp + (size_t)b * KP;
    dst[k] = hi; dst[1024 + k] = lo; dst[2048 + k] = hi;
    if (i == 0) { g_barcnt = 0; g_barsense = 0; }
}

// ---------------- grid barrier ----------------------------------------------
__device__ __forceinline__ void gbar(unsigned& phase) {
    phase++;
    __threadfence();
    __syncthreads();
    if (threadIdx.x == 0) {
        unsigned a = atomicAdd(&g_barcnt, 1);
        if (a == GRID_REC - 1) {
            g_barcnt = 0;
            __threadfence();
            g_barsense = phase;
        } else {
            while (g_barsense != phase) { __nanosleep(32); }
        }
    }
    __syncthreads();
    __threadfence();
}

// ---------------- big bf16 GEMM (unchanged, known-good) ---------------------
__global__ __launch_bounds__(256)
void gemm_bf16p(int a_sel, int w_base, int c_mode,
                const float* __restrict__ bias0, const float* __restrict__ bias1,
                const float* __restrict__ bias2, float* __restrict__ Cext) {
    const int z = blockIdx.z;
    const __nv_bfloat16* A = a_sel ? g_hsp : g_xp;
    const __nv_bfloat16* W = g_wp + (size_t)(w_base + z) * WPSZ;
    const float* bias = (z == 0) ? bias0 : (z == 1) ? bias1 : bias2;
    float* C = (c_mode == 1) ? Cext : (z == 0 ? g_xz : z == 1 ? g_xr : g_xn);

    __shared__ __nv_bfloat16 As[128 * LDT];
    __shared__ __nv_bfloat16 Bs[64 * LDT];

    const int m0 = blockIdx.y * 128, n0 = blockIdx.x * 64;
    const int t = threadIdx.x, lane = t & 31, w8 = t >> 5;
    const int wm = w8 >> 1, wn = w8 & 1;
    const int lr = t >> 3, lq = t & 7;

    float acc[2][4][4] = {};

    for (int k0 = 0; k0 < KP; k0 += 64) {
        #pragma unroll
        for (int p = 0; p < 4; ++p) {
            int r = lr + p * 32;
            ((uint4*)(As + r * LDT))[lq] =
                *((const uint4*)(A + (size_t)(m0 + r) * KP + k0) + lq);
        }
        #pragma unroll
        for (int p = 0; p < 2; ++p) {
            int r = lr + p * 32;
            ((uint4*)(Bs + r * LDT))[lq] =
                *((const uint4*)(W + (size_t)(n0 + r) * KP + k0) + lq);
        }
        __syncthreads();
        #pragma unroll
        for (int kk = 0; kk < 4; ++kk) {
            const int ks = kk * 16;
            uint32_t aF[2][4], bF[2][4];
            #pragma unroll
            for (int mi = 0; mi < 2; ++mi) {
                int arow = wm * 32 + mi * 16 + (lane & 15);
                int acol = ks + ((lane >> 4) << 3);
                ldsm_x4(aF[mi], smem_u32(As + arow * LDT + acol));
            }
            #pragma unroll
            for (int nq = 0; nq < 2; ++nq) {
                int brow = wn * 32 + nq * 16 + (lane & 7) + (((lane >> 4) & 1) << 3);
                int bcol = ks + (((lane >> 3) & 1) << 3);
                ldsm_x4(bF[nq], smem_u32(Bs + brow * LDT + bcol));
            }
            #pragma unroll
            for (int mi = 0; mi < 2; ++mi)
                #pragma unroll
                for (int nq = 0; nq < 2; ++nq) {
                    mma_bf16(acc[mi][2 * nq],     aF[mi], bF[nq][0], bF[nq][1]);
                    mma_bf16(acc[mi][2 * nq + 1], aF[mi], bF[nq][2], bF[nq][3]);
                }
        }
        __syncthreads();
    }

    #pragma unroll
    for (int mi = 0; mi < 2; ++mi)
        #pragma unroll
        for (int ni = 0; ni < 4; ++ni) {
            int row = m0 + wm * 32 + mi * 16 + (lane >> 2);
            int col = n0 + wn * 32 + ni * 8 + (lane & 3) * 2;
            float b0 = bias[col], b1 = bias[col + 1];
            float* a = acc[mi][ni];
            *(float2*)&C[(size_t)row * DH + col]       = make_float2(a[0] + b0, a[1] + b1);
            *(float2*)&C[(size_t)(row + 8) * DH + col] = make_float2(a[2] + b0, a[3] + b1);
        }
}

// ---------------- recurrence GEMM: 64x128 block tile, pipelined -------------
// 8 warps (2m x 4n), warp tile 32x32 (same inner loop as gemm_bf16p).
__device__ __forceinline__ void rec_gemm(
    const __nv_bfloat16* __restrict__ Ag,   // [64, KP] activations
    const __nv_bfloat16* __restrict__ Wg,   // weight rows n0..n0+127, pitch KP
    int k0, int nit,
    __nv_bfloat16 (*sA)[64 * LDT],
    __nv_bfloat16 (*sW)[128 * LDT],
    float acc[2][4][4]) {
    const int t = threadIdx.x, lane = t & 31, w8 = t >> 5;
    const int wm = w8 >> 2, wn = w8 & 3;

    auto load_stage = [&](int st, int kt) {
        const int kb = k0 + kt * 64;
        #pragma unroll
        for (int q = 0; q < 2; ++q) {
            int c = t + q * 256;                 // 512 chunks = 64x64 bf16
            int r = c >> 3, off = (c & 7) * 8;
            cp_async16(smem_u32(&sA[st][r * LDT + off]),
                       Ag + (size_t)r * KP + kb + off);
        }
        #pragma unroll
        for (int q = 0; q < 4; ++q) {
            int c = t + q * 256;                 // 1024 chunks = 128x64 bf16
            int r = c >> 3, off = (c & 7) * 8;
            cp_async16(smem_u32(&sW[st][r * LDT + off]),
                       Wg + (size_t)r * KP + kb + off);
        }
        cp_commit();
    };

    load_stage(0, 0);
    load_stage(1, 1);

    for (int kt = 0; kt < nit; ++kt) {
        cp_wait<1>();
        __syncthreads();
        const int st = kt % 3;
        #pragma unroll
        for (int kk = 0; kk < 4; ++kk) {
            const int ks = kk * 16;
            uint32_t aF[2][4], bF[2][4];
            #pragma unroll
            for (int mi = 0; mi < 2; ++mi) {
                int arow = wm * 32 + mi * 16 + (lane & 15);
                int acol = ks + ((lane >> 4) << 3);
                ldsm_x4(aF[mi], smem_u32(&sA[st][arow * LDT + acol]));
            }
            #pragma unroll
            for (int nq = 0; nq < 2; ++nq) {
                int brow = wn * 32 + nq * 16 + (lane & 7) + (((lane >> 4) & 1) << 3);
                int bcol = ks + (((lane >> 3) & 1) << 3);
                ldsm_x4(bF[nq], smem_u32(&sW[st][brow * LDT + bcol]));
            }
            #pragma unroll
            for (int mi = 0; mi < 2; ++mi)
                #pragma unroll
                for (int nq = 0; nq < 2; ++nq) {
                    mma_bf16(acc[mi][2 * nq],     aF[mi], bF[nq][0], bF[nq][1]);
                    mma_bf16(acc[mi][2 * nq + 1], aF[mi], bF[nq][2], bF[nq][3]);
                }
        }
        if (kt + 2 < nit) load_stage((kt + 2) % 3, kt + 2);
        else cp_commit();                         // empty group keeps wait<1> accounting
        __syncthreads();
    }
}

__device__ __forceinline__ void store_partial128(
    float* __restrict__ part, int n0, const float acc[2][4][4]) {
    const int lane = threadIdx.x & 31, w8 = threadIdx.x >> 5;
    const int wm = w8 >> 2, wn = w8 & 3;
    #pragma unroll
    for (int mi = 0; mi < 2; ++mi)
        #pragma unroll
        for (int ni = 0; ni < 4; ++ni) {
            int row = wm * 32 + mi * 16 + (lane >> 2);
            int col = n0 + wn * 32 + ni * 8 + (lane & 3) * 2;
            const float* a = acc[mi][ni];
            *(float2*)&part[(size_t)row * DH + col]       = make_float2(a[0], a[1]);
            *(float2*)&part[(size_t)(row + 8) * DH + col] = make_float2(a[2], a[3]);
        }
}

// ---------------- persistent recurrence (4 phases / 4 barriers per step) ----
__global__ __launch_bounds__(REC_THREADS)
void recurrence_kernel() {
    extern __shared__ char dynbuf[];
    __nv_bfloat16 (*sA)[64 * LDT]  = (__nv_bfloat16 (*)[64 * LDT])dynbuf;
    __nv_bfloat16 (*sW)[128 * LDT] =
        (__nv_bfloat16 (*)[128 * LDT])(dynbuf + 3 * 64 * LDT * 2);

    const int bid = blockIdx.x;
    const int tid = threadIdx.x;
    unsigned phase = 0;

    // phase A: gate(2) x ntile(8 of 128 cols) x ks(8 of 384)
    const int gateA = bid >> 6;
    const int subA  = bid & 63;
    const int n0A   = (subA >> 3) * 128;
    const int ksA   = subA & 7;
    const int k0A   = ksA * CH_ZR;
    const __nv_bfloat16* WA = g_wp + (size_t)(3 + gateA) * WPSZ + (size_t)n0A * KP;
    float* partA = g_pzr + (size_t)(gateA * KS_ZR + ksA) * BHD;

    // phase C: ntile(8 of 128 cols) x ks(16 of 192)
    const int n0C = (bid >> 4) * 128;
    const int ksC = bid & 15;
    const int k0C = ksC * CH_N;
    const __nv_bfloat16* WC = g_wp + (size_t)5 * WPSZ + (size_t)n0C * KP;
    float* partC = g_pn + (size_t)ksC * BHD;

    for (int s = 0; s < SEQ; ++s) {
        // ============ phase A: z,r partial GEMMs (A = g_hp) ============
        {
            float acc[2][4][4] = {};
            rec_gemm(g_hp, WA, k0A, CH_ZR / 64, sA, sW, acc);
            store_partial128(partA, n0A, acc);
        }
        gbar(phase);

        // ============ phase B: r reduce + sigmoid + rh tri-split ============
        {
            const float* xr = g_xr + (size_t)s * BHD;
            #pragma unroll
            for (int q = 0; q < 2; ++q) {
                int i = bid * 512 + q * 256 + tid;
                float tr = 0.f;
                #pragma unroll
                for (int ks = 0; ks < KS_ZR; ++ks)
                    tr += g_pzr[(size_t)(KS_ZR + ks) * BHD + i];
                float r = 1.f / (1.f + __expf(-(xr[i] + tr)));
                float rh = r * g_h[i];
                int b = i >> 10, k = i & 1023;
                __nv_bfloat16 hi, lo; trisplit(rh, hi, lo);
                __nv_bfloat16* dst = g_rhp + (size_t)b * KP;
                dst[k] = hi; dst[1024 + k] = lo; dst[2048 + k] = hi;
            }
        }
        gbar(phase);

        // ============ phase C: n partial GEMM (A = g_rhp) ============
        {
            float acc[2][4][4] = {};
            rec_gemm(g_rhp, WC, k0C, CH_N / 64, sA, sW, acc);
            store_partial128(partC, n0C, acc);
        }
        gbar(phase);

        // ============ phase D: z,n reduce + h update ============
        {
            const float* xz = g_xz + (size_t)s * BHD;
            const float* xn = g_xn + (size_t)s * BHD;
            #pragma unroll
            for (int q = 0; q < 2; ++q) {
                int i = bid * 512 + q * 256 + tid;
                float tz = 0.f;
                #pragma unroll
                for (int ks = 0; ks < KS_ZR; ++ks)
                    tz += g_pzr[(size_t)ks * BHD + i];
                float tn = 0.f;
                #pragma unroll
                for (int ks = 0; ks < KS_N; ++ks)
                    tn += g_pn[(size_t)ks * BHD + i];
                float zv = 1.f / (1.f + __expf(-(xz[i] + tz)));
                float nv = tanhf(xn[i] + tn);
                float h  = g_h[i];
                float hn = fmaf(zv, nv - h, h);
                g_h[i] = hn;
                int b = i >> 10, k = i & 1023;
                __nv_bfloat16 hi, lo; trisplit(hn, hi, lo);
                __nv_bfloat16* dh = g_hp + (size_t)b * KP;
                dh[k] = hi; dh[1024 + k] = lo; dh[2048 + k] = hi;
                __nv_bfloat16* ds = g_hsp + ((size_t)s * BAT + b) * KP;
                ds[k] = hi; ds[1024 + k] = lo; ds[2048 + k] = hi;
            }
        }
        gbar(phase);
    }
}

__global__ void copy_hlast_kernel(float* __restrict__ dst) {
    int i = blockIdx.x * 256 + threadIdx.x;
    dst[i] = g_h[i];
}

// ---------------- launch ----------------------------------------------------
extern "C" void kernel_launch(void* const* d_in, const int* in_sizes, int n_in,
                              void* d_out, int out_size) {
    const float* x   = (const float*)d_in[0];
    const float* h0  = (const float*)d_in[1];
    const float* Wxz = (const float*)d_in[2];
    const float* bxz = (const float*)d_in[3];
    const float* Whz = (const float*)d_in[4];
    const float* Wxr = (const float*)d_in[5];
    const float* bxr = (const float*)d_in[6];
    const float* Whr = (const float*)d_in[7];
    const float* Wxn = (const float*)d_in[8];
    const float* bxn = (const float*)d_in[9];
    const float* Whn = (const float*)d_in[10];
    const float* Why = (const float*)d_in[11];
    const float* bhy = (const float*)d_in[12];
    float* out = (float*)d_out;

    cudaFuncSetAttribute(recurrence_kernel,
                         cudaFuncAttributeMaxDynamicSharedMemorySize, REC_SMEM);

    conv_w_kernel<<<dim3(DH * DH / 256, 1, 7), 256>>>(Wxz, Wxr, Wxn, Whz, Whr, Whn, Why);
    conv_a_kernel<<<(size_t)MROWS * DH / 256, 256>>>(x);
    init_h_kernel<<<BHD / 256, 256>>>(h0);

    gemm_bf16p<<<dim3(DH / 64, MROWS / 128, 3), 256>>>(
        0, 0, 0, bxz, bxr, bxn, nullptr);

    recurrence_kernel<<<GRID_REC, REC_THREADS, REC_SMEM>>>();

    gemm_bf16p<<<dim3(DH / 64, MROWS / 128, 1), 256>>>(
        1, 6, 1, bhy, bhy, bhy, out);

    copy_hlast_kernel<<<BHD / 256, 256>>>(out + (size_t)MROWS * DH);
}

// round 7
// speedup vs baseline: 2.9948x; 1.1310x over previous
#include <cuda_runtime.h>
#include <cuda_bf16.h>
#include <cstdint>

#define SEQ   512
#define BAT   64
#define DH    1024
#define KP    3072                 // tri-split K' = 3*1024
#define MROWS (SEQ*BAT)            // 32768
#define BHD   (BAT*DH)             // 65536

#define GRID_REC 128
#define REC_THREADS 256
#define KS_ZR 8                    // zr chunk = 384
#define KS_N  16                   // n  chunk = 192
#define CH_ZR 384
#define CH_N  192
#define WPSZ  ((size_t)DH*KP)
#define LDT   72                   // smem row stride (bf16)
#define REC_SMEM (3*(64+128)*LDT*2)    // 82944
#define BIG_SMEM (3*(128+64)*LDT*2)    // 82944

// ---------------- device globals (no allocations allowed) -------------------
__device__ __nv_bfloat16 g_xp [(size_t)MROWS*KP];   // x tri-split (hi,lo,hi)
__device__ __nv_bfloat16 g_hsp[(size_t)MROWS*KP];   // hs tri-split
__device__ __nv_bfloat16 g_wp [7*WPSZ];             // weights tri-split (hi,hi,lo)
__device__ float g_xz[(size_t)SEQ*BHD];
__device__ float g_xr[(size_t)SEQ*BHD];
__device__ float g_xn[(size_t)SEQ*BHD];
__device__ float g_h [BHD];
__device__ __nv_bfloat16 g_hp [BAT*KP];             // h tri-split
__device__ __nv_bfloat16 g_rhp[BAT*KP];             // r*h tri-split
__device__ float g_pzr[2*KS_ZR*(size_t)BHD];        // z,r split-K partials
__device__ float g_pn [KS_N*(size_t)BHD];           // n split-K partials
__device__ unsigned g_barcnt;
__device__ unsigned g_barsense;

// ---------------- helpers ----------------------------------------------------
__device__ __forceinline__ void trisplit(float v, __nv_bfloat16& hi, __nv_bfloat16& lo) {
    hi = __float2bfloat16(v);
    lo = __float2bfloat16(v - __bfloat162float(hi));
}

__device__ __forceinline__ uint32_t smem_u32(const void* p) {
    return (uint32_t)__cvta_generic_to_shared(p);
}

__device__ __forceinline__ void ldsm_x4(uint32_t* r, uint32_t addr) {
    asm volatile("ldmatrix.sync.aligned.m8n8.x4.shared.b16 {%0,%1,%2,%3}, [%4];"
                 : "=r"(r[0]), "=r"(r[1]), "=r"(r[2]), "=r"(r[3]) : "r"(addr));
}

__device__ __forceinline__ void mma_bf16(float* d, const uint32_t* a,
                                         uint32_t b0, uint32_t b1) {
    asm volatile("mma.sync.aligned.m16n8k16.row.col.f32.bf16.bf16.f32 "
                 "{%0,%1,%2,%3},{%4,%5,%6,%7},{%8,%9},{%0,%1,%2,%3};"
                 : "+f"(d[0]), "+f"(d[1]), "+f"(d[2]), "+f"(d[3])
                 : "r"(a[0]), "r"(a[1]), "r"(a[2]), "r"(a[3]), "r"(b0), "r"(b1));
}

__device__ __forceinline__ void cp_async16(uint32_t saddr, const void* gptr) {
    asm volatile("cp.async.cg.shared.global [%0], [%1], 16;" :: "r"(saddr), "l"(gptr));
}
__device__ __forceinline__ void cp_commit() {
    asm volatile("cp.async.commit_group;");
}
template <int N>
__device__ __forceinline__ void cp_wait() {
    asm volatile("cp.async.wait_group %0;" :: "n"(N));
}

// ---------------- conversion kernels ----------------------------------------
__global__ void conv_a_kernel(const float* __restrict__ x) {
    size_t i = (size_t)blockIdx.x * 256 + threadIdx.x;
    float v = x[i];
    size_t m = i >> 10, k = i & 1023;
    __nv_bfloat16 hi, lo; trisplit(v, hi, lo);
    __nv_bfloat16* dst = g_xp + m * KP;
    dst[k] = hi; dst[1024 + k] = lo; dst[2048 + k] = hi;
}

__global__ void conv_w_kernel(const float* w0, const float* w1, const float* w2,
                              const float* w3, const float* w4, const float* w5,
                              const float* w6) {
    int z = blockIdx.z;
    const float* src = (z==0)?w0:(z==1)?w1:(z==2)?w2:(z==3)?w3:(z==4)?w4:(z==5)?w5:w6;
    size_t i = (size_t)blockIdx.x * 256 + threadIdx.x;
    float v = src[i];
    size_t row = i >> 10, k = i & 1023;
    __nv_bfloat16 hi, lo; trisplit(v, hi, lo);
    __nv_bfloat16* dst = g_wp + (size_t)z * WPSZ + row * KP;
    dst[k] = hi; dst[1024 + k] = hi; dst[2048 + k] = lo;
}

// ---------------- init -------------------------------------------------------
__global__ void init_h_kernel(const float* __restrict__ h0) {
    int i = blockIdx.x * 256 + threadIdx.x;
    float v = h0[i];
    g_h[i] = v;
    int b = i >> 10, k = i & 1023;
    __nv_bfloat16 hi, lo; trisplit(v, hi, lo);
    __nv_bfloat16* dst = g_hp + (size_t)b * KP;
    dst[k] = hi; dst[1024 + k] = lo; dst[2048 + k] = hi;
    if (i == 0) { g_barcnt = 0; g_barsense = 0; }
}

// ---------------- grid barrier (release/acquire, no heavy fences) -----------
__device__ __forceinline__ void gbar(unsigned& phase) {
    phase++;
    __syncthreads();
    if (threadIdx.x == 0) {
        unsigned one = 1, a;
        asm volatile("atom.add.release.gpu.u32 %0, [%1], %2;"
                     : "=r"(a) : "l"(&g_barcnt), "r"(one) : "memory");
        if (a == GRID_REC - 1) {
            g_barcnt = 0;
            asm volatile("st.release.gpu.u32 [%0], %1;"
                         :: "l"(&g_barsense), "r"(phase) : "memory");
        } else {
            unsigned v;
            do {
                asm volatile("ld.acquire.gpu.u32 %0, [%1];"
                             : "=r"(v) : "l"(&g_barsense) : "memory");
            } while (v != phase);
        }
    }
    __syncthreads();
}

// ---------------- big bf16 GEMM, 3-stage cp.async pipeline ------------------
// BM=128, BN=64, BK=64, 256 threads, 8 warps (4m x 2n), warp tile 32x32.
__global__ __launch_bounds__(256)
void gemm_bf16p(int a_sel, int w_base, int c_mode,
                const float* __restrict__ bias0, const float* __restrict__ bias1,
                const float* __restrict__ bias2, float* __restrict__ Cext) {
    const int z = blockIdx.z;
    const __nv_bfloat16* A = a_sel ? g_hsp : g_xp;
    const __nv_bfloat16* W = g_wp + (size_t)(w_base + z) * WPSZ;
    const float* bias = (z == 0) ? bias0 : (z == 1) ? bias1 : bias2;
    float* C = (c_mode == 1) ? Cext : (z == 0 ? g_xz : z == 1 ? g_xr : g_xn);

    extern __shared__ char dynsm[];
    __nv_bfloat16 (*sA)[128 * LDT] = (__nv_bfloat16 (*)[128 * LDT])dynsm;
    __nv_bfloat16 (*sB)[64 * LDT]  =
        (__nv_bfloat16 (*)[64 * LDT])(dynsm + 3 * 128 * LDT * 2);

    const int m0 = blockIdx.y * 128, n0 = blockIdx.x * 64;
    const int t = threadIdx.x, lane = t & 31, w8 = t >> 5;
    const int wm = w8 >> 1, wn = w8 & 1;

    auto load_stage = [&](int st, int kt) {
        const int kb = kt * 64;
        #pragma unroll
        for (int q = 0; q < 4; ++q) {              // A: 128x64 = 1024 chunks
            int c = t + q * 256;
            int r = c >> 3, off = (c & 7) * 8;
            cp_async16(smem_u32(&sA[st][r * LDT + off]),
                       A + (size_t)(m0 + r) * KP + kb + off);
        }
        #pragma unroll
        for (int q = 0; q < 2; ++q) {              // W: 64x64 = 512 chunks
            int c = t + q * 256;
            int r = c >> 3, off = (c & 7) * 8;
            cp_async16(smem_u32(&sB[st][r * LDT + off]),
                       W + (size_t)(n0 + r) * KP + kb + off);
        }
        cp_commit();
    };

    float acc[2][4][4] = {};
    load_stage(0, 0);
    load_stage(1, 1);

    const int NIT = KP / 64;                       // 48
    for (int kt = 0; kt < NIT; ++kt) {
        cp_wait<1>();
        __syncthreads();
        const int st = kt % 3;
        #pragma unroll
        for (int kk = 0; kk < 4; ++kk) {
            const int ks = kk * 16;
            uint32_t aF[2][4], bF[2][4];
            #pragma unroll
            for (int mi = 0; mi < 2; ++mi) {
                int arow = wm * 32 + mi * 16 + (lane & 15);
                int acol = ks + ((lane >> 4) << 3);
                ldsm_x4(aF[mi], smem_u32(&sA[st][arow * LDT + acol]));
            }
            #pragma unroll
            for (int nq = 0; nq < 2; ++nq) {
                int brow = wn * 32 + nq * 16 + (lane & 7) + (((lane >> 4) & 1) << 3);
                int bcol = ks + (((lane >> 3) & 1) << 3);
                ldsm_x4(bF[nq], smem_u32(&sB[st][brow * LDT + bcol]));
            }
            #pragma unroll
            for (int mi = 0; mi < 2; ++mi)
                #pragma unroll
                for (int nq = 0; nq < 2; ++nq) {
                    mma_bf16(acc[mi][2 * nq],     aF[mi], bF[nq][0], bF[nq][1]);
                    mma_bf16(acc[mi][2 * nq + 1], aF[mi], bF[nq][2], bF[nq][3]);
                }
        }
        if (kt + 2 < NIT) load_stage((kt + 2) % 3, kt + 2);
        else cp_commit();
        __syncthreads();
    }

    #pragma unroll
    for (int mi = 0; mi < 2; ++mi)
        #pragma unroll
        for (int ni = 0; ni < 4; ++ni) {
            int row = m0 + wm * 32 + mi * 16 + (lane >> 2);
            int col = n0 + wn * 32 + ni * 8 + (lane & 3) * 2;
            float b0 = bias[col], b1 = bias[col + 1];
            float* a = acc[mi][ni];
            *(float2*)&C[(size_t)row * DH + col]       = make_float2(a[0] + b0, a[1] + b1);
            *(float2*)&C[(size_t)(row + 8) * DH + col] = make_float2(a[2] + b0, a[3] + b1);
        }
}

// ---------------- recurrence GEMM: 64x128 block tile, pipelined -------------
// 8 warps (2m x 4n), warp tile 32x32.
__device__ __forceinline__ void rec_gemm(
    const __nv_bfloat16* __restrict__ Ag,
    const __nv_bfloat16* __restrict__ Wg,
    int k0, int nit,
    __nv_bfloat16 (*sA)[64 * LDT],
    __nv_bfloat16 (*sW)[128 * LDT],
    float acc[2][4][4]) {
    const int t = threadIdx.x, lane = t & 31, w8 = t >> 5;
    const int wm = w8 >> 2, wn = w8 & 3;

    auto load_stage = [&](int st, int kt) {
        const int kb = k0 + kt * 64;
        #pragma unroll
        for (int q = 0; q < 2; ++q) {
            int c = t + q * 256;
            int r = c >> 3, off = (c & 7) * 8;
            cp_async16(smem_u32(&sA[st][r * LDT + off]),
                       Ag + (size_t)r * KP + kb + off);
        }
        #pragma unroll
        for (int q = 0; q < 4; ++q) {
            int c = t + q * 256;
            int r = c >> 3, off = (c & 7) * 8;
            cp_async16(smem_u32(&sW[st][r * LDT + off]),
                       Wg + (size_t)r * KP + kb + off);
        }
        cp_commit();
    };

    load_stage(0, 0);
    load_stage(1, 1);

    for (int kt = 0; kt < nit; ++kt) {
        cp_wait<1>();
        __syncthreads();
        const int st = kt % 3;
        #pragma unroll
        for (int kk = 0; kk < 4; ++kk) {
            const int ks = kk * 16;
            uint32_t aF[2][4], bF[2][4];
            #pragma unroll
            for (int mi = 0; mi < 2; ++mi) {
                int arow = wm * 32 + mi * 16 + (lane & 15);
                int acol = ks + ((lane >> 4) << 3);
                ldsm_x4(aF[mi], smem_u32(&sA[st][arow * LDT + acol]));
            }
            #pragma unroll
            for (int nq = 0; nq < 2; ++nq) {
                int brow = wn * 32 + nq * 16 + (lane & 7) + (((lane >> 4) & 1) << 3);
                int bcol = ks + (((lane >> 3) & 1) << 3);
                ldsm_x4(bF[nq], smem_u32(&sW[st][brow * LDT + bcol]));
            }
            #pragma unroll
            for (int mi = 0; mi < 2; ++mi)
                #pragma unroll
                for (int nq = 0; nq < 2; ++nq) {
                    mma_bf16(acc[mi][2 * nq],     aF[mi], bF[nq][0], bF[nq][1]);
                    mma_bf16(acc[mi][2 * nq + 1], aF[mi], bF[nq][2], bF[nq][3]);
                }
        }
        if (kt + 2 < nit) load_stage((kt + 2) % 3, kt + 2);
        else cp_commit();
        __syncthreads();
    }
}

__device__ __forceinline__ void store_partial128(
    float* __restrict__ part, int n0, const float acc[2][4][4]) {
    const int lane = threadIdx.x & 31, w8 = threadIdx.x >> 5;
    const int wm = w8 >> 2, wn = w8 & 3;
    #pragma unroll
    for (int mi = 0; mi < 2; ++mi)
        #pragma unroll
        for (int ni = 0; ni < 4; ++ni) {
            int row = wm * 32 + mi * 16 + (lane >> 2);
            int col = n0 + wn * 32 + ni * 8 + (lane & 3) * 2;
            const float* a = acc[mi][ni];
            *(float2*)&part[(size_t)row * DH + col]       = make_float2(a[0], a[1]);
            *(float2*)&part[(size_t)(row + 8) * DH + col] = make_float2(a[2], a[3]);
        }
}

// ---------------- persistent recurrence (4 phases / 4 barriers per step) ----
__global__ __launch_bounds__(REC_THREADS)
void recurrence_kernel() {
    extern __shared__ char dynbuf[];
    __nv_bfloat16 (*sA)[64 * LDT]  = (__nv_bfloat16 (*)[64 * LDT])dynbuf;
    __nv_bfloat16 (*sW)[128 * LDT] =
        (__nv_bfloat16 (*)[128 * LDT])(dynbuf + 3 * 64 * LDT * 2);

    const int bid = blockIdx.x;
    const int tid = threadIdx.x;
    unsigned phase = 0;

    // phase A: gate(2) x ntile(8 of 128 cols) x ks(8 of 384)
    const int gateA = bid >> 6;
    const int subA  = bid & 63;
    const int n0A   = (subA >> 3) * 128;
    const int ksA   = subA & 7;
    const int k0A   = ksA * CH_ZR;
    const __nv_bfloat16* WA = g_wp + (size_t)(3 + gateA) * WPSZ + (size_t)n0A * KP;
    float* partA = g_pzr + (size_t)(gateA * KS_ZR + ksA) * BHD;

    // phase C: ntile(8 of 128 cols) x ks(16 of 192)
    const int n0C = (bid >> 4) * 128;
    const int ksC = bid & 15;
    const int k0C = ksC * CH_N;
    const __nv_bfloat16* WC = g_wp + (size_t)5 * WPSZ + (size_t)n0C * KP;
    float* partC = g_pn + (size_t)ksC * BHD;

    for (int s = 0; s < SEQ; ++s) {
        // ============ phase A: z,r partial GEMMs (A = g_hp) ============
        {
            float acc[2][4][4] = {};
            rec_gemm(g_hp, WA, k0A, CH_ZR / 64, sA, sW, acc);
            store_partial128(partA, n0A, acc);
        }
        gbar(phase);

        // ============ phase B: r reduce + sigmoid + rh tri-split ============
        {
            const float* xr = g_xr + (size_t)s * BHD;
            #pragma unroll
            for (int q = 0; q < 2; ++q) {
                int i = bid * 512 + q * 256 + tid;
                float tr = 0.f;
                #pragma unroll
                for (int ks = 0; ks < KS_ZR; ++ks)
                    tr += __ldcg(&g_pzr[(size_t)(KS_ZR + ks) * BHD + i]);
                float r = 1.f / (1.f + __expf(-(xr[i] + tr)));
                float rh = r * g_h[i];
                int b = i >> 10, k = i & 1023;
                __nv_bfloat16 hi, lo; trisplit(rh, hi, lo);
                __nv_bfloat16* dst = g_rhp + (size_t)b * KP;
                dst[k] = hi; dst[1024 + k] = lo; dst[2048 + k] = hi;
            }
        }
        gbar(phase);

        // ============ phase C: n partial GEMM (A = g_rhp) ============
        {
            float acc[2][4][4] = {};
            rec_gemm(g_rhp, WC, k0C, CH_N / 64, sA, sW, acc);
            store_partial128(partC, n0C, acc);
        }
        gbar(phase);

        // ============ phase D: z,n reduce + h update ============
        {
            const float* xz = g_xz + (size_t)s * BHD;
            const float* xn = g_xn + (size_t)s * BHD;
            #pragma unroll
            for (int q = 0; q < 2; ++q) {
                int i = bid * 512 + q * 256 + tid;
                float tz = 0.f;
                #pragma unroll
                for (int ks = 0; ks < KS_ZR; ++ks)
                    tz += __ldcg(&g_pzr[(size_t)ks * BHD + i]);
                float tn = 0.f;
                #pragma unroll
                for (int ks = 0; ks < KS_N; ++ks)
                    tn += __ldcg(&g_pn[(size_t)ks * BHD + i]);
                float zv = 1.f / (1.f + __expf(-(xz[i] + tz)));
                float nv = tanhf(xn[i] + tn);
                float h  = g_h[i];
                float hn = fmaf(zv, nv - h, h);
                g_h[i] = hn;
                int b = i >> 10, k = i & 1023;
                __nv_bfloat16 hi, lo; trisplit(hn, hi, lo);
                __nv_bfloat16* dh = g_hp + (size_t)b * KP;
                dh[k] = hi; dh[1024 + k] = lo; dh[2048 + k] = hi;
                __nv_bfloat16* ds = g_hsp + ((size_t)s * BAT + b) * KP;
                ds[k] = hi; ds[1024 + k] = lo; ds[2048 + k] = hi;
            }
        }
        gbar(phase);
    }
}

__global__ void copy_hlast_kernel(float* __restrict__ dst) {
    int i = blockIdx.x * 256 + threadIdx.x;
    dst[i] = g_h[i];
}

// ---------------- launch ----------------------------------------------------
extern "C" void kernel_launch(void* const* d_in, const int* in_sizes, int n_in,
                              void* d_out, int out_size) {
    const float* x   = (const float*)d_in[0];
    const float* h0  = (const float*)d_in[1];
    const float* Wxz = (const float*)d_in[2];
    const float* bxz = (const float*)d_in[3];
    const float* Whz = (const float*)d_in[4];
    const float* Wxr = (const float*)d_in[5];
    const float* bxr = (const float*)d_in[6];
    const float* Whr = (const float*)d_in[7];
    const float* Wxn = (const float*)d_in[8];
    const float* bxn = (const float*)d_in[9];
    const float* Whn = (const float*)d_in[10];
    const float* Why = (const float*)d_in[11];
    const float* bhy = (const float*)d_in[12];
    float* out = (float*)d_out;

    cudaFuncSetAttribute(recurrence_kernel,
                         cudaFuncAttributeMaxDynamicSharedMemorySize, REC_SMEM);
    cudaFuncSetAttribute(gemm_bf16p,
                         cudaFuncAttributeMaxDynamicSharedMemorySize, BIG_SMEM);

    conv_w_kernel<<<dim3(DH * DH / 256, 1, 7), 256>>>(Wxz, Wxr, Wxn, Whz, Whr, Whn, Why);
    conv_a_kernel<<<(size_t)MROWS * DH / 256, 256>>>(x);
    init_h_kernel<<<BHD / 256, 256>>>(h0);

    gemm_bf16p<<<dim3(DH / 64, MROWS / 128, 3), 256, BIG_SMEM>>>(
        0, 0, 0, bxz, bxr, bxn, nullptr);

    recurrence_kernel<<<GRID_REC, REC_THREADS, REC_SMEM>>>();

    gemm_bf16p<<<dim3(DH / 64, MROWS / 128, 1), 256, BIG_SMEM>>>(
        1, 6, 1, bhy, bhy, bhy, out);

    copy_hlast_kernel<<<BHD / 256, 256>>>(out + (size_t)MROWS * DH);
}